// round 1
// baseline (speedup 1.0000x reference)
#include <cuda_runtime.h>
#include <cstdint>

// Problem constants (fixed by the dataset)
#define NN 100000
#define DD 64
#define EE 1600000
#define NET 3   // num edge types

// ---------------------------------------------------------------------------
// Scratch: per-etype accumulators (sum of x[src] per dst) and degree counters.
// __device__ globals are the sanctioned scratch mechanism (no runtime alloc).
// ---------------------------------------------------------------------------
__device__ __align__(16) float g_agg[(size_t)NET * NN * DD];  // 76.8 MB
__device__ int g_deg[NET * NN];

// ---------------------------------------------------------------------------
// Kernel 1: zero accumulators + degree counters (float4 stores)
// ---------------------------------------------------------------------------
__global__ void zero_kernel() {
    int idx = blockIdx.x * blockDim.x + threadIdx.x;
    const int n4 = NET * NN * DD / 4;  // 4,800,000 float4s
    float4* a4 = reinterpret_cast<float4*>(g_agg);
    if (idx < n4) a4[idx] = make_float4(0.f, 0.f, 0.f, 0.f);
    if (idx < NET * NN) g_deg[idx] = 0;
}

// ---------------------------------------------------------------------------
// Kernel 2: edge scatter. 16 threads per edge; each thread moves one float4
// of x[src] into agg[etype][dst] via vectorized global reduction.
// gridDim.y = etype. Lane 0 of each edge increments the degree counter.
// ---------------------------------------------------------------------------
struct EdgePtrs {
    const int* src[NET];
    const int* dst[NET];
};

__global__ void __launch_bounds__(256) scatter_kernel(EdgePtrs ep,
                                                      const float* __restrict__ x,
                                                      int E) {
    const int et = blockIdx.y;
    long long gid = (long long)blockIdx.x * blockDim.x + threadIdx.x;
    int e = (int)(gid >> 4);
    int lane = (int)(gid & 15);
    if (e >= E) return;

    int s = __ldg(ep.src[et] + e);
    int d = __ldg(ep.dst[et] + e);

    // gather one float4 of x[s]
    const float4* xs = reinterpret_cast<const float4*>(x) + (long long)s * (DD / 4) + lane;
    float4 v = __ldg(xs);

    // vectorized reduction into the per-etype accumulator (16B-aligned)
    float* base = g_agg + ((long long)et * NN + d) * DD + lane * 4;
    asm volatile("red.global.add.v4.f32 [%0], {%1,%2,%3,%4};"
                 :: "l"(base), "f"(v.x), "f"(v.y), "f"(v.z), "f"(v.w)
                 : "memory");

    if (lane == 0) atomicAdd(&g_deg[et * NN + d], 1);
}

// ---------------------------------------------------------------------------
// Kernel 3: finalize.  h[v,j] = sum_i [deg_i(v)>0] * ( (agg_i[v]/deg_i) . W_i[:,j] + b_i[j] )
//
// W_i transposed into smem as Wt[i][j][k] with row stride 68 floats:
//  - 68*4 = 272 bytes, 16B aligned -> LDS.128 legal
//  - bank pattern (4j + k) mod 32 -> the 8 lanes of each 128B phase hit
//    disjoint 4-bank groups -> conflict-free LDS.128.
// Thread = (node, j). 256 threads = 4 nodes/block-iteration; block grid-strides
// over nodes so W is staged from L2 only once per block.
// ---------------------------------------------------------------------------
#define WT_STRIDE 68
#define SMEM_FLOATS (NET * DD * WT_STRIDE + NET * DD)   // Wt + bias
#define SMEM_BYTES  (SMEM_FLOATS * 4)                   // 52,992 B

__global__ void __launch_bounds__(256) finalize_kernel(
    const float* __restrict__ W0, const float* __restrict__ b0,
    const float* __restrict__ W1, const float* __restrict__ b1,
    const float* __restrict__ W2, const float* __restrict__ b2,
    float* __restrict__ out, int N)
{
    extern __shared__ float sm[];
    float* Wt = sm;                              // [3][64][68]
    float* bs = sm + NET * DD * WT_STRIDE;       // [3][64]

    const float* Ws[NET]  = {W0, W1, W2};
    const float* bps[NET] = {b0, b1, b2};

    // stage W transposed (+bias) into smem
    for (int t = threadIdx.x; t < NET * DD * DD; t += blockDim.x) {
        int i = t / (DD * DD);
        int r = t - i * DD * DD;
        int k = r / DD;        // input dim
        int j = r - k * DD;    // output dim
        Wt[(i * DD + j) * WT_STRIDE + k] = Ws[i][r];
    }
    for (int t = threadIdx.x; t < NET * DD; t += blockDim.x)
        bs[t] = bps[t / DD][t % DD];
    __syncthreads();

    const int j = threadIdx.x & (DD - 1);
    const int nodeInBlk = threadIdx.x >> 6;      // 0..3

    for (int v0 = blockIdx.x * 4; v0 < N; v0 += gridDim.x * 4) {
        int v = v0 + nodeInBlk;
        if (v >= N) continue;

        float acc = 0.f;
        #pragma unroll
        for (int i = 0; i < NET; i++) {
            int dg = g_deg[i * NN + v];          // uniform across the warp
            if (dg > 0) {
                float inv = 1.0f / (float)dg;
                const float4* u4 = reinterpret_cast<const float4*>(
                    g_agg + ((long long)i * NN + v) * DD);
                const float* wrow = Wt + (i * DD + j) * WT_STRIDE;
                float s = 0.f;
                #pragma unroll
                for (int k4 = 0; k4 < DD / 4; k4++) {
                    float4 u = __ldg(u4 + k4);
                    float4 w = *reinterpret_cast<const float4*>(wrow + k4 * 4);
                    s += u.x * w.x + u.y * w.y + u.z * w.z + u.w * w.w;
                }
                acc += s * inv + bs[i * DD + j];
            }
        }
        out[(long long)v * DD + j] = acc;
    }
}

// ---------------------------------------------------------------------------
// Launch
// ---------------------------------------------------------------------------
extern "C" void kernel_launch(void* const* d_in, const int* in_sizes, int n_in,
                              void* d_out, int out_size) {
    // Disambiguate metadata ordering:
    //   signature order: x, W0,b0, W1,b1, W2,b2, src0,dst0, src1,dst1, src2,dst2
    //   dict order:      x, W0,b0,src0,dst0, W1,b1,src1,dst1, W2,b2,src2,dst2
    // in_sizes[3] is 4096 (W1) in signature order, 1.6M (src0) in dict order.
    const float* x;
    const float *W[NET], *B[NET];
    const int *SRC[NET], *DST[NET];

    x = (const float*)d_in[0];
    bool dict_order = (in_sizes[3] > 100000);
    if (dict_order) {
        for (int i = 0; i < NET; i++) {
            W[i]   = (const float*)d_in[1 + 4 * i];
            B[i]   = (const float*)d_in[2 + 4 * i];
            SRC[i] = (const int*)  d_in[3 + 4 * i];
            DST[i] = (const int*)  d_in[4 + 4 * i];
        }
    } else {
        for (int i = 0; i < NET; i++) {
            W[i]   = (const float*)d_in[1 + 2 * i];
            B[i]   = (const float*)d_in[2 + 2 * i];
            SRC[i] = (const int*)  d_in[7 + 2 * i];
            DST[i] = (const int*)  d_in[8 + 2 * i];
        }
    }

    int E = dict_order ? in_sizes[3] : in_sizes[7];
    int N = in_sizes[0] / DD;
    float* out = (float*)d_out;

    // opt-in to >48KB dynamic smem for finalize (idempotent, capture-safe)
    cudaFuncSetAttribute(finalize_kernel,
                         cudaFuncAttributeMaxDynamicSharedMemorySize, SMEM_BYTES);

    // 1) zero scratch
    {
        int n4 = NET * NN * DD / 4;
        int blocks = (n4 + 255) / 256;
        zero_kernel<<<blocks, 256>>>();
    }

    // 2) scatter all 3 etypes in one launch (gridDim.y = etype)
    {
        EdgePtrs ep;
        for (int i = 0; i < NET; i++) { ep.src[i] = SRC[i]; ep.dst[i] = DST[i]; }
        long long threads = (long long)E * 16;
        dim3 grid((unsigned)((threads + 255) / 256), NET, 1);
        scatter_kernel<<<grid, 256>>>(ep, x, E);
    }

    // 3) finalize: GEMM + mean + bias, grid-strided so W stages once per block
    {
        int blocks = 1184;  // 8/SM target; grid-stride handles the rest
        finalize_kernel<<<blocks, 256, SMEM_BYTES>>>(
            W[0], B[0], W[1], B[1], W[2], B[2], out, N);
    }
}

// round 2
// speedup vs baseline: 1.7581x; 1.7581x over previous
#include <cuda_runtime.h>
#include <cstdint>

#define NN 100000
#define DD 64
#define EE 1600000
#define NET 3
#define TOT (NET * NN)           // 300,000 (node, etype) pairs
#define SCAN_BLK 512
#define NB1 ((TOT + SCAN_BLK - 1) / SCAN_BLK)   // 586

// ---------------------------------------------------------------------------
// Device-global scratch (no runtime allocation allowed)
// ---------------------------------------------------------------------------
__device__ int g_deg[TOT];          // per-pair degree histogram
__device__ int g_excl[TOT];         // block-local exclusive scan
__device__ int g_bsum[1024];        // per-block totals
__device__ int g_boff[1024];        // exclusive scan of block totals
__device__ int g_off[TOT + 1];      // CSR offsets
__device__ int g_cursor[TOT];       // fill cursors (copy of offsets)
__device__ int g_srcs[NET * EE];    // src indices sorted by (etype,dst)  19.2 MB
__device__ __align__(16) float g_agg[(size_t)TOT * DD];   // 76.8 MB sums

struct EdgePtrs {
    const int* src[NET];
    const int* dst[NET];
};

// ---------------------------------------------------------------------------
// 1) zero the degree histogram (tiny: 1.2 MB)
// ---------------------------------------------------------------------------
__global__ void zero_deg_kernel() {
    int i = blockIdx.x * blockDim.x + threadIdx.x;
    if (i < TOT) g_deg[i] = 0;
}

// ---------------------------------------------------------------------------
// 2) count: histogram dst per (etype, node) with int atomics
// ---------------------------------------------------------------------------
__global__ void __launch_bounds__(256) count_kernel(EdgePtrs ep, int E) {
    int et = blockIdx.y;
    int e = blockIdx.x * blockDim.x + threadIdx.x;
    if (e >= E) return;
    int d = __ldg(ep.dst[et] + e);
    atomicAdd(&g_deg[et * NN + d], 1);
}

// ---------------------------------------------------------------------------
// 3a) scan pass 1: per-block exclusive scan + block totals
// ---------------------------------------------------------------------------
__global__ void __launch_bounds__(SCAN_BLK) scan1_kernel() {
    int gid = blockIdx.x * SCAN_BLK + threadIdx.x;
    int lane = threadIdx.x & 31, wid = threadIdx.x >> 5;
    int v = (gid < TOT) ? g_deg[gid] : 0;

    int inc = v;
    #pragma unroll
    for (int o = 1; o < 32; o <<= 1) {
        int y = __shfl_up_sync(0xffffffffu, inc, o);
        if (lane >= o) inc += y;
    }
    __shared__ int ws[16];
    if (lane == 31) ws[wid] = inc;
    __syncthreads();
    if (wid == 0 && lane < 16) {
        int s = ws[lane];
        #pragma unroll
        for (int o = 1; o < 16; o <<= 1) {
            int y = __shfl_up_sync(0x0000ffffu, s, o);
            if (lane >= o) s += y;
        }
        ws[lane] = s;   // inclusive
    }
    __syncthreads();
    int base = wid ? ws[wid - 1] : 0;
    if (gid < TOT) g_excl[gid] = base + inc - v;
    if (threadIdx.x == 0) g_bsum[blockIdx.x] = ws[15];
}

// ---------------------------------------------------------------------------
// 3b) scan pass 2: exclusive scan of block totals (single 1024-thread block)
// ---------------------------------------------------------------------------
__global__ void __launch_bounds__(1024) scan2_kernel(int nb) {
    int tid = threadIdx.x, lane = tid & 31, wid = tid >> 5;
    int v = (tid < nb) ? g_bsum[tid] : 0;
    int inc = v;
    #pragma unroll
    for (int o = 1; o < 32; o <<= 1) {
        int y = __shfl_up_sync(0xffffffffu, inc, o);
        if (lane >= o) inc += y;
    }
    __shared__ int ws[32];
    if (lane == 31) ws[wid] = inc;
    __syncthreads();
    if (wid == 0) {
        int s = ws[lane];
        #pragma unroll
        for (int o = 1; o < 32; o <<= 1) {
            int y = __shfl_up_sync(0xffffffffu, s, o);
            if (lane >= o) s += y;
        }
        ws[lane] = s;
    }
    __syncthreads();
    int base = wid ? ws[wid - 1] : 0;
    g_boff[tid] = base + inc - v;
}

// ---------------------------------------------------------------------------
// 3c) scan pass 3: final offsets + cursor init
// ---------------------------------------------------------------------------
__global__ void __launch_bounds__(SCAN_BLK) scan3_kernel(int totalE) {
    int gid = blockIdx.x * SCAN_BLK + threadIdx.x;
    if (gid < TOT) {
        int off = g_excl[gid] + g_boff[blockIdx.x];
        g_off[gid] = off;
        g_cursor[gid] = off;
    }
    if (gid == 0) g_off[TOT] = totalE;
}

// ---------------------------------------------------------------------------
// 4) fill: bucket src indices by (etype, dst)
// ---------------------------------------------------------------------------
__global__ void __launch_bounds__(256) fill_kernel(EdgePtrs ep, int E) {
    int et = blockIdx.y;
    int e = blockIdx.x * blockDim.x + threadIdx.x;
    if (e >= E) return;
    int s = __ldg(ep.src[et] + e);
    int d = __ldg(ep.dst[et] + e);
    int pos = atomicAdd(&g_cursor[et * NN + d], 1);
    g_srcs[pos] = s;
}

// ---------------------------------------------------------------------------
// 5) gather: one warp per (etype,node) pair. Atomic-free accumulation of
//    x[src] rows; float2 per lane (32 lanes * 8B = 256B coalesced row reads).
// ---------------------------------------------------------------------------
__global__ void __launch_bounds__(256) gather_kernel(const float* __restrict__ x) {
    int p = (blockIdx.x * blockDim.x + threadIdx.x) >> 5;
    int lane = threadIdx.x & 31;
    if (p >= TOT) return;

    int begin = __ldg(&g_off[p]);
    int end   = __ldg(&g_off[p + 1]);

    const float2* x2 = reinterpret_cast<const float2*>(x);
    float ax = 0.f, ay = 0.f;

    int k = begin;
    for (; k + 4 <= end; k += 4) {
        int s0 = __ldg(&g_srcs[k]);
        int s1 = __ldg(&g_srcs[k + 1]);
        int s2 = __ldg(&g_srcs[k + 2]);
        int s3 = __ldg(&g_srcs[k + 3]);
        float2 v0 = __ldg(&x2[(long long)s0 * 32 + lane]);
        float2 v1 = __ldg(&x2[(long long)s1 * 32 + lane]);
        float2 v2 = __ldg(&x2[(long long)s2 * 32 + lane]);
        float2 v3 = __ldg(&x2[(long long)s3 * 32 + lane]);
        ax += (v0.x + v1.x) + (v2.x + v3.x);
        ay += (v0.y + v1.y) + (v2.y + v3.y);
    }
    for (; k < end; k++) {
        int s = __ldg(&g_srcs[k]);
        float2 v = __ldg(&x2[(long long)s * 32 + lane]);
        ax += v.x; ay += v.y;
    }

    float2* o2 = reinterpret_cast<float2*>(g_agg + (size_t)p * DD);
    o2[lane] = make_float2(ax, ay);
}

// ---------------------------------------------------------------------------
// 6) finalize: h[v,j] = sum_i [deg>0] ( (agg_i[v]/deg_i) . W_i[:,j] + b_i[j] )
//    W transposed to smem, stride 68 for conflict-free LDS.128.
// ---------------------------------------------------------------------------
#define WT_STRIDE 68
#define SMEM_FLOATS (NET * DD * WT_STRIDE + NET * DD)
#define SMEM_BYTES  (SMEM_FLOATS * 4)

__global__ void __launch_bounds__(256) finalize_kernel(
    const float* __restrict__ W0, const float* __restrict__ b0,
    const float* __restrict__ W1, const float* __restrict__ b1,
    const float* __restrict__ W2, const float* __restrict__ b2,
    float* __restrict__ out, int N)
{
    extern __shared__ float sm[];
    float* Wt = sm;                          // [3][64][68]
    float* bs = sm + NET * DD * WT_STRIDE;   // [3][64]

    const float* Ws[NET]  = {W0, W1, W2};
    const float* bps[NET] = {b0, b1, b2};

    for (int t = threadIdx.x; t < NET * DD * DD; t += blockDim.x) {
        int i = t / (DD * DD);
        int r = t - i * DD * DD;
        int k = r / DD;
        int j = r - k * DD;
        Wt[(i * DD + j) * WT_STRIDE + k] = Ws[i][r];
    }
    for (int t = threadIdx.x; t < NET * DD; t += blockDim.x)
        bs[t] = bps[t / DD][t % DD];
    __syncthreads();

    const int j = threadIdx.x & (DD - 1);
    const int nodeInBlk = threadIdx.x >> 6;

    for (int v0 = blockIdx.x * 4; v0 < N; v0 += gridDim.x * 4) {
        int v = v0 + nodeInBlk;
        if (v >= N) continue;

        float acc = 0.f;
        #pragma unroll
        for (int i = 0; i < NET; i++) {
            int p = i * NN + v;
            int dg = __ldg(&g_off[p + 1]) - __ldg(&g_off[p]);
            if (dg > 0) {
                float inv = 1.0f / (float)dg;
                const float4* u4 = reinterpret_cast<const float4*>(
                    g_agg + (size_t)p * DD);
                const float* wrow = Wt + (i * DD + j) * WT_STRIDE;
                float s = 0.f;
                #pragma unroll
                for (int k4 = 0; k4 < DD / 4; k4++) {
                    float4 u = __ldg(u4 + k4);
                    float4 w = *reinterpret_cast<const float4*>(wrow + k4 * 4);
                    s += u.x * w.x + u.y * w.y + u.z * w.z + u.w * w.w;
                }
                acc += s * inv + bs[i * DD + j];
            }
        }
        out[(long long)v * DD + j] = acc;
    }
}

// ---------------------------------------------------------------------------
// Launch
// ---------------------------------------------------------------------------
extern "C" void kernel_launch(void* const* d_in, const int* in_sizes, int n_in,
                              void* d_out, int out_size) {
    const float* x = (const float*)d_in[0];
    const float *W[NET], *B[NET];
    const int *SRC[NET], *DST[NET];

    bool dict_order = (in_sizes[3] > 100000);
    if (dict_order) {
        for (int i = 0; i < NET; i++) {
            W[i]   = (const float*)d_in[1 + 4 * i];
            B[i]   = (const float*)d_in[2 + 4 * i];
            SRC[i] = (const int*)  d_in[3 + 4 * i];
            DST[i] = (const int*)  d_in[4 + 4 * i];
        }
    } else {
        for (int i = 0; i < NET; i++) {
            W[i]   = (const float*)d_in[1 + 2 * i];
            B[i]   = (const float*)d_in[2 + 2 * i];
            SRC[i] = (const int*)  d_in[7 + 2 * i];
            DST[i] = (const int*)  d_in[8 + 2 * i];
        }
    }

    int E = dict_order ? in_sizes[3] : in_sizes[7];
    int N = in_sizes[0] / DD;
    float* out = (float*)d_out;

    cudaFuncSetAttribute(finalize_kernel,
                         cudaFuncAttributeMaxDynamicSharedMemorySize, SMEM_BYTES);

    EdgePtrs ep;
    for (int i = 0; i < NET; i++) { ep.src[i] = SRC[i]; ep.dst[i] = DST[i]; }

    dim3 egrid((unsigned)((E + 255) / 256), NET, 1);

    // 1) zero degree histogram
    zero_deg_kernel<<<(TOT + 255) / 256, 256>>>();
    // 2) count
    count_kernel<<<egrid, 256>>>(ep, E);
    // 3) scan (offsets + cursors)
    scan1_kernel<<<NB1, SCAN_BLK>>>();
    scan2_kernel<<<1, 1024>>>(NB1);
    scan3_kernel<<<NB1, SCAN_BLK>>>(NET * E);
    // 4) bucket src by (etype, dst)
    fill_kernel<<<egrid, 256>>>(ep, E);
    // 5) atomic-free gather: warp per (etype,node)
    {
        int warps = TOT;
        int blocks = (warps * 32 + 255) / 256;
        gather_kernel<<<blocks, 256>>>(x);
    }
    // 6) GEMM + mean + bias
    finalize_kernel<<<1184, 256, SMEM_BYTES>>>(
        W[0], B[0], W[1], B[1], W[2], B[2], out, N);
}

// round 3
// speedup vs baseline: 1.7972x; 1.0222x over previous
#include <cuda_runtime.h>
#include <cuda_fp16.h>
#include <cstdint>

#define NN 100000
#define DD 64
#define EE 1600000
#define NET 3
#define TOT (NET * NN)           // 300,000 (node, etype) pairs
#define SCAN_BLK 512
#define NB1 ((TOT + SCAN_BLK - 1) / SCAN_BLK)   // 586

// ---------------------------------------------------------------------------
// Device-global scratch (no runtime allocation allowed)
// ---------------------------------------------------------------------------
__device__ int g_deg[TOT];            // per-pair degree histogram
__device__ int g_excl[TOT];           // block-local exclusive scan
__device__ int g_bsum[1024];          // per-block totals
__device__ int g_boff[1024];          // exclusive scan of block totals
__device__ int g_off[TOT + 1];        // CSR offsets
__device__ int g_rank[NET * EE];      // within-bucket rank per edge (from count)
__device__ int g_srcs[NET * EE];      // src indices sorted by (etype,dst)
__device__ __align__(16) __half g_xh[(size_t)NN * DD];       // fp16 x cache 12.8MB
__device__ __align__(16) float g_agg[(size_t)TOT * DD];      // fp32 sums 76.8MB

struct EdgePtrs {
    const int* src[NET];
    const int* dst[NET];
};

// packed fp32x2 FMA (PTX-only; sm_100+)
#define FMA_F32X2(d, a, b, c) \
    asm("fma.rn.f32x2 %0, %1, %2, %3;" : "=l"(d) : "l"(a), "l"(b), "l"(c))

// ---------------------------------------------------------------------------
// 0) convert x to fp16 cache (float4 in -> 2x half2 out, packed 8B store)
// ---------------------------------------------------------------------------
__global__ void __launch_bounds__(256) convert_x_kernel(const float* __restrict__ x) {
    int i = blockIdx.x * blockDim.x + threadIdx.x;
    const int n4 = NN * DD / 4;
    if (i >= n4) return;
    float4 v = __ldg(reinterpret_cast<const float4*>(x) + i);
    __half2 h0 = __floats2half2_rn(v.x, v.y);
    __half2 h1 = __floats2half2_rn(v.z, v.w);
    uint2 pk;
    pk.x = *reinterpret_cast<unsigned*>(&h0);
    pk.y = *reinterpret_cast<unsigned*>(&h1);
    reinterpret_cast<uint2*>(g_xh)[i] = pk;
}

// ---------------------------------------------------------------------------
// 1) zero the degree histogram
// ---------------------------------------------------------------------------
__global__ void zero_deg_kernel() {
    int i = blockIdx.x * blockDim.x + threadIdx.x;
    if (i < TOT) g_deg[i] = 0;
}

// ---------------------------------------------------------------------------
// 2) count: histogram dst per (etype,node); atomic return value IS the
//    within-bucket rank -> store it (coalesced) so fill needs no atomics.
// ---------------------------------------------------------------------------
__global__ void __launch_bounds__(256) count_kernel(EdgePtrs ep, int E) {
    int et = blockIdx.y;
    int e = blockIdx.x * blockDim.x + threadIdx.x;
    if (e >= E) return;
    int d = __ldg(ep.dst[et] + e);
    int r = atomicAdd(&g_deg[et * NN + d], 1);
    g_rank[et * E + e] = r;
}

// ---------------------------------------------------------------------------
// 3a) scan pass 1: per-block exclusive scan + block totals
// ---------------------------------------------------------------------------
__global__ void __launch_bounds__(SCAN_BLK) scan1_kernel() {
    int gid = blockIdx.x * SCAN_BLK + threadIdx.x;
    int lane = threadIdx.x & 31, wid = threadIdx.x >> 5;
    int v = (gid < TOT) ? g_deg[gid] : 0;

    int inc = v;
    #pragma unroll
    for (int o = 1; o < 32; o <<= 1) {
        int y = __shfl_up_sync(0xffffffffu, inc, o);
        if (lane >= o) inc += y;
    }
    __shared__ int ws[16];
    if (lane == 31) ws[wid] = inc;
    __syncthreads();
    if (wid == 0 && lane < 16) {
        int s = ws[lane];
        #pragma unroll
        for (int o = 1; o < 16; o <<= 1) {
            int y = __shfl_up_sync(0x0000ffffu, s, o);
            if (lane >= o) s += y;
        }
        ws[lane] = s;   // inclusive
    }
    __syncthreads();
    int base = wid ? ws[wid - 1] : 0;
    if (gid < TOT) g_excl[gid] = base + inc - v;
    if (threadIdx.x == 0) g_bsum[blockIdx.x] = ws[15];
}

// ---------------------------------------------------------------------------
// 3b) scan pass 2: exclusive scan of block totals
// ---------------------------------------------------------------------------
__global__ void __launch_bounds__(1024) scan2_kernel(int nb) {
    int tid = threadIdx.x, lane = tid & 31, wid = tid >> 5;
    int v = (tid < nb) ? g_bsum[tid] : 0;
    int inc = v;
    #pragma unroll
    for (int o = 1; o < 32; o <<= 1) {
        int y = __shfl_up_sync(0xffffffffu, inc, o);
        if (lane >= o) inc += y;
    }
    __shared__ int ws[32];
    if (lane == 31) ws[wid] = inc;
    __syncthreads();
    if (wid == 0) {
        int s = ws[lane];
        #pragma unroll
        for (int o = 1; o < 32; o <<= 1) {
            int y = __shfl_up_sync(0xffffffffu, s, o);
            if (lane >= o) s += y;
        }
        ws[lane] = s;
    }
    __syncthreads();
    int base = wid ? ws[wid - 1] : 0;
    g_boff[tid] = base + inc - v;
}

// ---------------------------------------------------------------------------
// 3c) scan pass 3: final offsets
// ---------------------------------------------------------------------------
__global__ void __launch_bounds__(SCAN_BLK) scan3_kernel(int totalE) {
    int gid = blockIdx.x * SCAN_BLK + threadIdx.x;
    if (gid < TOT) g_off[gid] = g_excl[gid] + g_boff[blockIdx.x];
    if (gid == 0) g_off[TOT] = totalE;
}

// ---------------------------------------------------------------------------
// 4) fill: bucket src indices by (etype,dst) -- atomic-free (uses rank)
// ---------------------------------------------------------------------------
__global__ void __launch_bounds__(256) fill_kernel(EdgePtrs ep, int E) {
    int et = blockIdx.y;
    int e = blockIdx.x * blockDim.x + threadIdx.x;
    if (e >= E) return;
    int s = __ldg(ep.src[et] + e);
    int d = __ldg(ep.dst[et] + e);
    int pos = __ldg(&g_off[et * NN + d]) + __ldg(&g_rank[et * E + e]);
    g_srcs[pos] = s;
}

// ---------------------------------------------------------------------------
// 5) gather: one warp per (etype,node) pair. fp16 x rows (half2 per lane =
//    128B/warp/row), fp32 accumulation, unroll 8 for MLP depth.
// ---------------------------------------------------------------------------
__global__ void __launch_bounds__(256) gather_kernel() {
    int p = (blockIdx.x * blockDim.x + threadIdx.x) >> 5;
    int lane = threadIdx.x & 31;
    if (p >= TOT) return;

    int begin = __ldg(&g_off[p]);
    int end   = __ldg(&g_off[p + 1]);

    const __half2* xh2 = reinterpret_cast<const __half2*>(g_xh);
    float ax = 0.f, ay = 0.f;

    int k = begin;
    for (; k + 8 <= end; k += 8) {
        int s0 = __ldg(&g_srcs[k]);
        int s1 = __ldg(&g_srcs[k + 1]);
        int s2 = __ldg(&g_srcs[k + 2]);
        int s3 = __ldg(&g_srcs[k + 3]);
        int s4 = __ldg(&g_srcs[k + 4]);
        int s5 = __ldg(&g_srcs[k + 5]);
        int s6 = __ldg(&g_srcs[k + 6]);
        int s7 = __ldg(&g_srcs[k + 7]);
        __half2 h0 = __ldg(&xh2[(size_t)s0 * 32 + lane]);
        __half2 h1 = __ldg(&xh2[(size_t)s1 * 32 + lane]);
        __half2 h2 = __ldg(&xh2[(size_t)s2 * 32 + lane]);
        __half2 h3 = __ldg(&xh2[(size_t)s3 * 32 + lane]);
        __half2 h4 = __ldg(&xh2[(size_t)s4 * 32 + lane]);
        __half2 h5 = __ldg(&xh2[(size_t)s5 * 32 + lane]);
        __half2 h6 = __ldg(&xh2[(size_t)s6 * 32 + lane]);
        __half2 h7 = __ldg(&xh2[(size_t)s7 * 32 + lane]);
        float2 v0 = __half22float2(h0); float2 v1 = __half22float2(h1);
        float2 v2 = __half22float2(h2); float2 v3 = __half22float2(h3);
        float2 v4 = __half22float2(h4); float2 v5 = __half22float2(h5);
        float2 v6 = __half22float2(h6); float2 v7 = __half22float2(h7);
        ax += ((v0.x + v1.x) + (v2.x + v3.x)) + ((v4.x + v5.x) + (v6.x + v7.x));
        ay += ((v0.y + v1.y) + (v2.y + v3.y)) + ((v4.y + v5.y) + (v6.y + v7.y));
    }
    for (; k < end; k++) {
        int s = __ldg(&g_srcs[k]);
        float2 v = __half22float2(__ldg(&xh2[(size_t)s * 32 + lane]));
        ax += v.x; ay += v.y;
    }

    float2* o2 = reinterpret_cast<float2*>(g_agg + (size_t)p * DD);
    o2[lane] = make_float2(ax, ay);
}

// ---------------------------------------------------------------------------
// 6) finalize via packed f32x2 FMAs:
//    h[v,j] = sum_i [deg>0] ( (agg_i[v]/deg_i) . W_i[:,j] + b_i[j] )
// ---------------------------------------------------------------------------
#define WT_STRIDE 68
#define SMEM_FLOATS (NET * DD * WT_STRIDE + NET * DD)
#define SMEM_BYTES  (SMEM_FLOATS * 4)

__global__ void __launch_bounds__(256) finalize_kernel(
    const float* __restrict__ W0, const float* __restrict__ b0,
    const float* __restrict__ W1, const float* __restrict__ b1,
    const float* __restrict__ W2, const float* __restrict__ b2,
    float* __restrict__ out, int N)
{
    extern __shared__ float sm[];
    float* Wt = sm;                          // [3][64][68] transposed weights
    float* bs = sm + NET * DD * WT_STRIDE;   // [3][64]

    const float* Ws[NET]  = {W0, W1, W2};
    const float* bps[NET] = {b0, b1, b2};

    for (int t = threadIdx.x; t < NET * DD * DD; t += blockDim.x) {
        int i = t / (DD * DD);
        int r = t - i * DD * DD;
        int k = r / DD;
        int j = r - k * DD;
        Wt[(i * DD + j) * WT_STRIDE + k] = Ws[i][r];
    }
    for (int t = threadIdx.x; t < NET * DD; t += blockDim.x)
        bs[t] = bps[t / DD][t % DD];
    __syncthreads();

    const int j = threadIdx.x & (DD - 1);
    const int nodeInBlk = threadIdx.x >> 6;

    for (int v0 = blockIdx.x * 4; v0 < N; v0 += gridDim.x * 4) {
        int v = v0 + nodeInBlk;
        if (v >= N) continue;

        float acc = 0.f;
        #pragma unroll
        for (int i = 0; i < NET; i++) {
            int p = i * NN + v;
            int dg = __ldg(&g_off[p + 1]) - __ldg(&g_off[p]);
            if (dg > 0) {
                float inv = 1.0f / (float)dg;
                const ulonglong2* u16 = reinterpret_cast<const ulonglong2*>(
                    g_agg + (size_t)p * DD);
                const ulonglong2* w16 = reinterpret_cast<const ulonglong2*>(
                    Wt + (i * DD + j) * WT_STRIDE);
                unsigned long long a0 = 0ull, a1 = 0ull;  // (0.f,0.f) packed
                #pragma unroll
                for (int q = 0; q < 16; q++) {
                    ulonglong2 uu = u16[q];
                    ulonglong2 ww = w16[q];
                    FMA_F32X2(a0, uu.x, ww.x, a0);
                    FMA_F32X2(a1, uu.y, ww.y, a1);
                }
                float2 f0 = *reinterpret_cast<float2*>(&a0);
                float2 f1 = *reinterpret_cast<float2*>(&a1);
                float s = (f0.x + f0.y) + (f1.x + f1.y);
                acc += s * inv + bs[i * DD + j];
            }
        }
        out[(long long)v * DD + j] = acc;
    }
}

// ---------------------------------------------------------------------------
// Launch
// ---------------------------------------------------------------------------
extern "C" void kernel_launch(void* const* d_in, const int* in_sizes, int n_in,
                              void* d_out, int out_size) {
    const float* x = (const float*)d_in[0];
    const float *W[NET], *B[NET];
    const int *SRC[NET], *DST[NET];

    bool dict_order = (in_sizes[3] > 100000);
    if (dict_order) {
        for (int i = 0; i < NET; i++) {
            W[i]   = (const float*)d_in[1 + 4 * i];
            B[i]   = (const float*)d_in[2 + 4 * i];
            SRC[i] = (const int*)  d_in[3 + 4 * i];
            DST[i] = (const int*)  d_in[4 + 4 * i];
        }
    } else {
        for (int i = 0; i < NET; i++) {
            W[i]   = (const float*)d_in[1 + 2 * i];
            B[i]   = (const float*)d_in[2 + 2 * i];
            SRC[i] = (const int*)  d_in[7 + 2 * i];
            DST[i] = (const int*)  d_in[8 + 2 * i];
        }
    }

    int E = dict_order ? in_sizes[3] : in_sizes[7];
    int N = in_sizes[0] / DD;
    float* out = (float*)d_out;

    cudaFuncSetAttribute(finalize_kernel,
                         cudaFuncAttributeMaxDynamicSharedMemorySize, SMEM_BYTES);

    EdgePtrs ep;
    for (int i = 0; i < NET; i++) { ep.src[i] = SRC[i]; ep.dst[i] = DST[i]; }

    dim3 egrid((unsigned)((E + 255) / 256), NET, 1);

    // 0) fp16 x cache
    convert_x_kernel<<<(NN * DD / 4 + 255) / 256, 256>>>(x);
    // 1) zero degree histogram
    zero_deg_kernel<<<(TOT + 255) / 256, 256>>>();
    // 2) count + rank
    count_kernel<<<egrid, 256>>>(ep, E);
    // 3) scan -> CSR offsets
    scan1_kernel<<<NB1, SCAN_BLK>>>();
    scan2_kernel<<<1, 1024>>>(NB1);
    scan3_kernel<<<NB1, SCAN_BLK>>>(NET * E);
    // 4) bucket src by (etype,dst), atomic-free
    fill_kernel<<<egrid, 256>>>(ep, E);
    // 5) atomic-free gather (fp16 rows, fp32 accumulate)
    gather_kernel<<<(TOT * 32 + 255) / 256, 256>>>();
    // 6) GEMM + mean + bias (packed f32x2 FMAs)
    finalize_kernel<<<1184, 256, SMEM_BYTES>>>(
        W[0], B[0], W[1], B[1], W[2], B[2], out, N);
}